// round 5
// baseline (speedup 1.0000x reference)
#include <cuda_runtime.h>
#include <cuda_bf16.h>
#include <math.h>
#include <stdint.h>

typedef __nv_bfloat16 bf16;

// ---------------- problem constants ----------------
#define BB 16
#define TT 512
#define DIN 1024
#define HH 256
#define NN 64
#define TOPK 8
#define NCLS 2
#define KBRIDGE (DIN * 9)      // 9216
#define KCONV (HH * 3)         // 768
#define MROWS (BB * TT)        // 8192
#define NROWS (BB * NN)        // 1024

// ---------------- PTX helpers ----------------
__device__ __forceinline__ uint32_t smem_u32(const void* p) {
    uint32_t a;
    asm("{ .reg .u64 t; cvta.to.shared.u64 t, %1; cvt.u32.u64 %0, t; }" : "=r"(a) : "l"(p));
    return a;
}
#define CP_ASYNC16(dst, src) \
    asm volatile("cp.async.cg.shared.global [%0], [%1], 16;" :: "r"(dst), "l"(src) : "memory")
#define CP_COMMIT() asm volatile("cp.async.commit_group;" ::: "memory")
#define CP_WAIT(N)  asm volatile("cp.async.wait_group %0;" :: "n"(N) : "memory")
#define LDSM_X4(r0, r1, r2, r3, a) \
    asm volatile("ldmatrix.sync.aligned.m8n8.x4.shared.b16 {%0,%1,%2,%3}, [%4];" \
        : "=r"(r0), "=r"(r1), "=r"(r2), "=r"(r3) : "r"(a))
#define MMA_BF16(c, a0, a1, a2, a3, b0, b1) \
    asm volatile("mma.sync.aligned.m16n8k16.row.col.f32.bf16.bf16.f32 " \
        "{%0,%1,%2,%3}, {%4,%5,%6,%7}, {%8,%9}, {%0,%1,%2,%3};" \
        : "+f"((c)[0]), "+f"((c)[1]), "+f"((c)[2]), "+f"((c)[3]) \
        : "r"(a0), "r"(a1), "r"(a2), "r"(a3), "r"(b0), "r"(b1))
#define STS128Z(addr) \
    asm volatile("st.shared.v4.b32 [%0], {%1,%1,%1,%1};" :: "r"(addr), "r"(0u) : "memory")
#define STS64(addr, r0, r1) \
    asm volatile("st.shared.v2.b32 [%0], {%1,%2};" :: "r"(addr), "r"(r0), "r"(r1) : "memory")

// ---------------- scratch ----------------
__device__ bf16 g_wh[HH * KBRIDGE];        // bridge weights (hi)
__device__ bf16 g_wl[HH * KBRIDGE];
__device__ bf16 g_h1h[MROWS * HH];         // bridge out split
__device__ bf16 g_h1l[MROWS * HH];
__device__ bf16 g_wch[HH * KCONV];
__device__ bf16 g_wcl[HH * KCONV];
__device__ bf16 g_y1h[MROWS * HH];
__device__ bf16 g_y1l[MROWS * HH];
__device__ float g_y2[MROWS * HH];
__device__ float g_hn[NROWS * HH];
__device__ bf16 g_hnh[NROWS * HH];
__device__ bf16 g_hnl[NROWS * HH];
__device__ bf16 g_wth[HH * HH];
__device__ bf16 g_wtl[HH * HH];
__device__ float g_hw[NROWS * HH];
__device__ float g_s[NROWS];
__device__ float g_d[NROWS];
__device__ unsigned long long g_adj[BB * NN];
__device__ float g_ln[NROWS * HH];

// ---------------- math helpers ----------------
__device__ __forceinline__ float silu_f(float x) { return x * (1.f / (1.f + expf(-x))); }
__device__ __forceinline__ float selu_f(float x) {
    const float a = 1.6732632423543772f, s = 1.0507009873554805f;
    return x > 0.f ? s * x : s * a * expm1f(x);
}
__device__ __forceinline__ void split_bf16(float v, bf16& h, bf16& l) {
    h = __float2bfloat16_rn(v);
    l = __float2bfloat16_rn(v - __bfloat162float(h));
}
union Pack2 { bf16 b[2]; uint32_t u; };
union Pack4 { bf16 b[4]; uint2 u; };
__device__ __forceinline__ uint32_t pack2(bf16 a, bf16 b) {
    Pack2 p; p.b[0] = a; p.b[1] = b; return p.u;
}
__device__ __forceinline__ void bsplines8(float x, float* out) {
    const float h = 0.4f;
    float b[11];
#pragma unroll
    for (int j = 0; j < 11; j++) {
        float gj = (float)(j - 3) * h - 1.0f;
        float gj1 = (float)(j - 2) * h - 1.0f;
        b[j] = (x >= gj && x < gj1) ? 1.f : 0.f;
    }
#pragma unroll
    for (int k = 1; k <= 3; k++) {
        float inv = 1.f / ((float)k * h);
#pragma unroll
        for (int j = 0; j < 11; j++) {
            if (j < 11 - k) {
                float gj = (float)(j - 3) * h - 1.0f;
                float gjk1 = (float)(j + k - 2) * h - 1.0f;
                b[j] = (x - gj) * inv * b[j] + (gjk1 - x) * inv * b[j + 1];
            }
        }
    }
#pragma unroll
    for (int j = 0; j < 8; j++) out[j] = b[j];
}

// ---------------- weight prep kernels ----------------
__global__ void build_wcat_bf16(const float* __restrict__ bw, const float* __restrict__ sw,
                                const float* __restrict__ sc) {
    int idx = blockIdx.x * blockDim.x + threadIdx.x;
    if (idx >= HH * DIN) return;
    int i = idx % DIN, o = idx / DIN;
    size_t base = (size_t)o * KBRIDGE + i;
    bf16 h, l;
    split_bf16(bw[idx], h, l);
    g_wh[base] = h; g_wl[base] = l;
    float scale = sc[idx];
#pragma unroll
    for (int c = 0; c < 8; c++) {
        split_bf16(sw[(size_t)idx * 8 + c] * scale, h, l);
        size_t p = base + (size_t)(c + 1) * DIN;
        g_wh[p] = h; g_wl[p] = l;
    }
}

__global__ void conv_w_bf16(const float* __restrict__ w) {
    int idx = blockIdx.x * blockDim.x + threadIdx.x;
    if (idx >= HH * HH) return;
    int i = idx % HH, o = idx / HH;
#pragma unroll
    for (int j = 0; j < 3; j++) {
        bf16 h, l;
        split_bf16(w[((size_t)o * HH + i) * 3 + j], h, l);
        size_t p = (size_t)o * KCONV + j * HH + i;
        g_wch[p] = h; g_wcl[p] = l;
    }
}

__global__ void gatwt_bf16(const float* __restrict__ w) {
    int idx = blockIdx.x * blockDim.x + threadIdx.x;
    if (idx >= HH * HH) return;
    int k = idx % HH, n = idx / HH;
    bf16 h, l;
    split_bf16(w[(size_t)k * HH + n], h, l);
    g_wth[idx] = h; g_wtl[idx] = l;
}

// ================= fused feature-gen + bridge GEMM =================
// C[m, 0:256] = A(features of x) @ W^T, bf16 hi/lo 3-product.
// CTA: 256 thr, tile 64(M) x 256(N), K processed as 32 i-chunks x 9 groups (BK=32).
#define F_SROW 80
#define F_GSZ (64 * F_SROW)          // 5120 per group per array
#define F_BYTES (9 * F_GSZ)          // 46080
#define BR_BSTG (256 * F_SROW)       // 20480 per array
#define BR_STAGE (2 * BR_BSTG)       // 40960 per stage (hi+lo)
#define BR_SMEM (2 * F_BYTES + 2 * BR_STAGE)   // 174080

__global__ __launch_bounds__(256, 1) void bridge_gemm_fused(
    const float* __restrict__ x,
    const bf16* __restrict__ Bh, const bf16* __restrict__ Bl,
    bf16* __restrict__ Ch, bf16* __restrict__ Cl) {
    extern __shared__ char smem[];
    uint32_t s0 = smem_u32(smem);
    uint32_t sFh = s0, sFl = s0 + F_BYTES, sB = s0 + 2 * F_BYTES;

    int tid = threadIdx.x, lane = tid & 31, wid = tid >> 5;
    int wm = wid & 1, wn = wid >> 1;
    int bm = blockIdx.x * 64;

    int aRow = wm * 32 + (lane & 15);
    int aCol = (lane >> 4) * 8;
    int bRow = wn * 64 + (lane & 7) + ((lane >> 4) << 3);
    int bCol = ((lane >> 3) & 1) * 8;

    float acc[2][8][4];
#pragma unroll
    for (int i = 0; i < 2; i++)
#pragma unroll
        for (int j = 0; j < 8; j++)
#pragma unroll
            for (int q = 0; q < 4; q++) acc[i][j][q] = 0.f;

    // feature thread mapping: 64 rows x 32 cols, thread -> (row, 8 cols)
    int fr = tid >> 2, fc = (tid & 3) * 8;
    const float* xrow = x + (size_t)(bm + fr) * DIN + fc;

    auto issueB = [&](int s, int kcol) {
#pragma unroll
        for (int i = 0; i < 4; i++) {
            int q = i * 256 + tid;
            int r = q >> 2, c = q & 3;
            uint32_t d = sB + (uint32_t)(s * BR_STAGE + r * F_SROW + c * 16);
            size_t go = (size_t)r * KBRIDGE + kcol + c * 8;
            CP_ASYNC16(d, Bh + go);
            CP_ASYNC16(d + BR_BSTG, Bl + go);
        }
    };

    issueB(0, 0);
    CP_COMMIT();

    int step = 0;
    for (int ic = 0; ic < 32; ic++) {
        int i0 = ic * 32;
        // ---- feature phase (overlaps pending cp.async of this ic's first B) ----
#pragma unroll
        for (int half = 0; half < 2; half++) {
            float4 xq = *reinterpret_cast<const float4*>(xrow + i0 + half * 4);
            float xv[4] = {xq.x, xq.y, xq.z, xq.w};
            Pack4 PH[9], PL[9];
#pragma unroll
            for (int j = 0; j < 4; j++) {
                float v = xv[j];
                split_bf16(silu_f(v), PH[0].b[j], PL[0].b[j]);
                float bs[8];
                bsplines8(v, bs);
#pragma unroll
                for (int c = 0; c < 8; c++) split_bf16(bs[c], PH[c + 1].b[j], PL[c + 1].b[j]);
            }
#pragma unroll
            for (int g = 0; g < 9; g++) {
                uint32_t off = (uint32_t)(g * F_GSZ + fr * F_SROW + (fc + half * 4) * 2);
                STS64(sFh + off, PH[g].u.x, PH[g].u.y);
                STS64(sFl + off, PL[g].u.x, PL[g].u.y);
            }
        }
        __syncthreads();

        // ---- 9 MMA steps (one per feature group) ----
        for (int g = 0; g < 9; g++) {
            if (step + 1 < 288) {
                int ng = g + 1, nic = ic;
                if (ng == 9) { ng = 0; nic = ic + 1; }
                issueB((step + 1) & 1, ng * 1024 + nic * 32);
                CP_COMMIT();
                CP_WAIT(1);
            } else {
                CP_WAIT(0);
            }
            __syncthreads();

            int s = step & 1;
            uint32_t fbh = sFh + (uint32_t)(g * F_GSZ);
            uint32_t fbl = sFl + (uint32_t)(g * F_GSZ);
            uint32_t bbh = sB + (uint32_t)(s * BR_STAGE);
            uint32_t bbl = bbh + BR_BSTG;
#pragma unroll
            for (int kk = 0; kk < 2; kk++) {
                uint32_t ah[2][4], al[2][4];
#pragma unroll
                for (int mt = 0; mt < 2; mt++) {
                    uint32_t ao = (uint32_t)((aRow + mt * 16) * F_SROW + (aCol + kk * 16) * 2);
                    LDSM_X4(ah[mt][0], ah[mt][1], ah[mt][2], ah[mt][3], fbh + ao);
                    LDSM_X4(al[mt][0], al[mt][1], al[mt][2], al[mt][3], fbl + ao);
                }
#pragma unroll
                for (int nt2 = 0; nt2 < 4; nt2++) {
                    uint32_t bo = (uint32_t)((bRow + nt2 * 16) * F_SROW + (bCol + kk * 16) * 2);
                    uint32_t bh[4], bl[4];
                    LDSM_X4(bh[0], bh[1], bh[2], bh[3], bbh + bo);
                    LDSM_X4(bl[0], bl[1], bl[2], bl[3], bbl + bo);
#pragma unroll
                    for (int mt = 0; mt < 2; mt++) {
                        int n0 = nt2 * 2, n1 = n0 + 1;
                        MMA_BF16(acc[mt][n0], ah[mt][0], ah[mt][1], ah[mt][2], ah[mt][3], bh[0], bh[1]);
                        MMA_BF16(acc[mt][n0], ah[mt][0], ah[mt][1], ah[mt][2], ah[mt][3], bl[0], bl[1]);
                        MMA_BF16(acc[mt][n0], al[mt][0], al[mt][1], al[mt][2], al[mt][3], bh[0], bh[1]);
                        MMA_BF16(acc[mt][n1], ah[mt][0], ah[mt][1], ah[mt][2], ah[mt][3], bh[2], bh[3]);
                        MMA_BF16(acc[mt][n1], ah[mt][0], ah[mt][1], ah[mt][2], ah[mt][3], bl[2], bl[3]);
                        MMA_BF16(acc[mt][n1], al[mt][0], al[mt][1], al[mt][2], al[mt][3], bh[2], bh[3]);
                    }
                }
            }
            __syncthreads();
            step++;
        }
    }

    // epilogue: split bf16 out
    int rbase = bm + wm * 32 + (lane >> 2);
    int cbase = wn * 64 + (lane & 3) * 2;
#pragma unroll
    for (int mt = 0; mt < 2; mt++) {
#pragma unroll
        for (int nt = 0; nt < 8; nt++) {
            int r = rbase + mt * 16;
            int c = cbase + nt * 8;
            bf16 h0, l0, h1, l1;
            split_bf16(acc[mt][nt][0], h0, l0);
            split_bf16(acc[mt][nt][1], h1, l1);
            *reinterpret_cast<uint32_t*>(Ch + (size_t)r * 256 + c) = pack2(h0, h1);
            *reinterpret_cast<uint32_t*>(Cl + (size_t)r * 256 + c) = pack2(l0, l1);
            split_bf16(acc[mt][nt][2], h0, l0);
            split_bf16(acc[mt][nt][3], h1, l1);
            *reinterpret_cast<uint32_t*>(Ch + (size_t)(r + 8) * 256 + c) = pack2(h0, h1);
            *reinterpret_cast<uint32_t*>(Cl + (size_t)(r + 8) * 256 + c) = pack2(l0, l1);
        }
    }
}

// ================= generic split-bf16 GEMM (convs + GAT) =================
// SHIFT=1: implicit im2col, A[row,k] = Y[row + k/256 - 1, k%256] (zfill at batch edge).
// EPI: 0 = fp32; 1 = selu(x+bias) fp32; 3 = selu(x+bias) split bf16.
#define BK 64
#define SROW 144
#define A_STG (64 * SROW)        // 9216
#define B_STG (256 * SROW)       // 36864
#define GEMM_SMEM (4 * A_STG + 4 * B_STG)   // 184320

template <int EPI, int SHIFT>
__global__ __launch_bounds__(256, 1) void gemm_mma(
    const bf16* __restrict__ Ah, const bf16* __restrict__ Al,
    const bf16* __restrict__ Bh, const bf16* __restrict__ Bl,
    float* __restrict__ Cf, bf16* __restrict__ Ch, bf16* __restrict__ Cl,
    int K, const float* __restrict__ bias) {
    extern __shared__ char smem[];
    uint32_t s0 = smem_u32(smem);
    uint32_t sAh = s0, sAl = s0 + 2 * A_STG;
    uint32_t sBh = s0 + 4 * A_STG, sBl = sBh + 2 * B_STG;

    int tid = threadIdx.x, lane = tid & 31, wid = tid >> 5;
    int wm = wid & 1, wn = wid >> 1;
    int bm = blockIdx.x * 64;
    const int nc = K / BK;

    int aRow = wm * 32 + (lane & 15);
    int aCol = (lane >> 4) * 8;
    int bRow = wn * 64 + (lane & 7) + ((lane >> 4) << 3);
    int bCol = ((lane >> 3) & 1) * 8;

    float acc[2][8][4];
#pragma unroll
    for (int i = 0; i < 2; i++)
#pragma unroll
        for (int j = 0; j < 8; j++)
#pragma unroll
            for (int q = 0; q < 4; q++) acc[i][j][q] = 0.f;

    auto issue = [&](int stage, int k0) {
#pragma unroll
        for (int i = 0; i < 2; i++) {
            int q = i * 256 + tid;
            int r = q >> 3, c = q & 7;
            uint32_t dh = sAh + (uint32_t)(stage * A_STG + r * SROW + c * 16);
            uint32_t dl = sAl + (uint32_t)(stage * A_STG + r * SROW + c * 16);
            if (SHIFT) {
                int k = k0 + c * 8;
                int j = k >> 8, cc = k & 255;
                int grow = bm + r;
                int tj = (grow & 511) + j - 1;
                if (tj >= 0 && tj < 512) {
                    size_t go = (size_t)(grow + j - 1) * 256 + cc;
                    CP_ASYNC16(dh, Ah + go);
                    CP_ASYNC16(dl, Al + go);
                } else {
                    STS128Z(dh);
                    STS128Z(dl);
                }
            } else {
                size_t go = (size_t)(bm + r) * K + k0 + c * 8;
                CP_ASYNC16(dh, Ah + go);
                CP_ASYNC16(dl, Al + go);
            }
        }
#pragma unroll
        for (int i = 0; i < 8; i++) {
            int q = i * 256 + tid;
            int r = q >> 3, c = q & 7;
            uint32_t d = (uint32_t)(stage * B_STG + r * SROW + c * 16);
            size_t go = (size_t)r * K + k0 + c * 8;
            CP_ASYNC16(sBh + d, Bh + go);
            CP_ASYNC16(sBl + d, Bl + go);
        }
    };

    issue(0, 0);
    CP_COMMIT();

    for (int kc = 0; kc < nc; kc++) {
        if (kc + 1 < nc) {
            issue((kc + 1) & 1, (kc + 1) * BK);
            CP_COMMIT();
            CP_WAIT(1);
        } else {
            CP_WAIT(0);
        }
        __syncthreads();
        uint32_t stA = (uint32_t)((kc & 1) * A_STG);
        uint32_t stB = (uint32_t)((kc & 1) * B_STG);
#pragma unroll
        for (int kk = 0; kk < 4; kk++) {
            uint32_t ah[2][4], al[2][4];
#pragma unroll
            for (int mt = 0; mt < 2; mt++) {
                uint32_t ao = stA + (uint32_t)((aRow + mt * 16) * SROW + (aCol + kk * 16) * 2);
                LDSM_X4(ah[mt][0], ah[mt][1], ah[mt][2], ah[mt][3], sAh + ao);
                LDSM_X4(al[mt][0], al[mt][1], al[mt][2], al[mt][3], sAl + ao);
            }
#pragma unroll
            for (int nt2 = 0; nt2 < 4; nt2++) {
                uint32_t bo = stB + (uint32_t)((bRow + nt2 * 16) * SROW + (bCol + kk * 16) * 2);
                uint32_t bh[4], bl[4];
                LDSM_X4(bh[0], bh[1], bh[2], bh[3], sBh + bo);
                LDSM_X4(bl[0], bl[1], bl[2], bl[3], sBl + bo);
#pragma unroll
                for (int mt = 0; mt < 2; mt++) {
                    int n0 = nt2 * 2, n1 = n0 + 1;
                    MMA_BF16(acc[mt][n0], ah[mt][0], ah[mt][1], ah[mt][2], ah[mt][3], bh[0], bh[1]);
                    MMA_BF16(acc[mt][n0], ah[mt][0], ah[mt][1], ah[mt][2], ah[mt][3], bl[0], bl[1]);
                    MMA_BF16(acc[mt][n0], al[mt][0], al[mt][1], al[mt][2], al[mt][3], bh[0], bh[1]);
                    MMA_BF16(acc[mt][n1], ah[mt][0], ah[mt][1], ah[mt][2], ah[mt][3], bh[2], bh[3]);
                    MMA_BF16(acc[mt][n1], ah[mt][0], ah[mt][1], ah[mt][2], ah[mt][3], bl[2], bl[3]);
                    MMA_BF16(acc[mt][n1], al[mt][0], al[mt][1], al[mt][2], al[mt][3], bh[2], bh[3]);
                }
            }
        }
        __syncthreads();
    }

    // epilogue
    int rbase = bm + wm * 32 + (lane >> 2);
    int cbase = wn * 64 + (lane & 3) * 2;
#pragma unroll
    for (int mt = 0; mt < 2; mt++) {
#pragma unroll
        for (int nt = 0; nt < 8; nt++) {
            int r = rbase + mt * 16;
            int c = cbase + nt * 8;
            float v0 = acc[mt][nt][0], v1 = acc[mt][nt][1];
            float w0 = acc[mt][nt][2], w1 = acc[mt][nt][3];
            if (EPI >= 1) {
                float b0 = bias[c], b1 = bias[c + 1];
                v0 = selu_f(v0 + b0); v1 = selu_f(v1 + b1);
                w0 = selu_f(w0 + b0); w1 = selu_f(w1 + b1);
            }
            if (EPI == 3) {
                bf16 h0, l0, h1, l1;
                split_bf16(v0, h0, l0); split_bf16(v1, h1, l1);
                *reinterpret_cast<uint32_t*>(Ch + (size_t)r * 256 + c) = pack2(h0, h1);
                *reinterpret_cast<uint32_t*>(Cl + (size_t)r * 256 + c) = pack2(l0, l1);
                split_bf16(w0, h0, l0); split_bf16(w1, h1, l1);
                *reinterpret_cast<uint32_t*>(Ch + (size_t)(r + 8) * 256 + c) = pack2(h0, h1);
                *reinterpret_cast<uint32_t*>(Cl + (size_t)(r + 8) * 256 + c) = pack2(l0, l1);
            } else {
                *reinterpret_cast<float2*>(Cf + (size_t)r * 256 + c) = make_float2(v0, v1);
                *reinterpret_cast<float2*>(Cf + (size_t)(r + 8) * 256 + c) = make_float2(w0, w1);
            }
        }
    }
}

// ---------------- pool + pos (+ adj zero, + split) ----------------
__global__ void pool_pos(const float* __restrict__ y2, const float* __restrict__ pos) {
    int idx = blockIdx.x * blockDim.x + threadIdx.x;
    if (idx < BB * NN) g_adj[idx] = 0ull;
    if (idx >= BB * NN * HH) return;
    int c = idx % HH;
    int n = (idx / HH) % NN;
    int b = idx / (HH * NN);
    float s = 0.f;
#pragma unroll
    for (int t = 0; t < 8; t++) s += y2[((size_t)b * TT + n * 8 + t) * HH + c];
    float v = s * 0.125f + pos[(size_t)n * HH + c];
    size_t o = ((size_t)b * NN + n) * HH + c;
    g_hn[o] = v;
    bf16 h, l;
    split_bf16(v, h, l);
    g_hnh[o] = h; g_hnl[o] = l;
}

// ---------------- adjacency ----------------
__global__ void adj_topk() {
    int b = blockIdx.x / NN, n = blockIdx.x % NN;
    __shared__ float sc[NN];
    int m = threadIdx.x;
    const float* hb = g_hn + (size_t)b * NN * HH;
    float s = 0.f;
    for (int k = 0; k < HH; k++) s = fmaf(hb[(size_t)n * HH + k], hb[(size_t)m * HH + k], s);
    sc[m] = s;
    __syncthreads();
    if (m == 0) {
        unsigned long long mask = 1ull << n;
        int sel[TOPK];
#pragma unroll 1
        for (int it = 0; it < TOPK; it++) {
            float best = -INFINITY; int bi = 0;
            for (int j = 0; j < NN; j++)
                if (sc[j] > best) { best = sc[j]; bi = j; }
            sel[it] = bi;
            sc[bi] = -INFINITY;
            mask |= 1ull << bi;
        }
        atomicOr(&g_adj[b * NN + n], mask);
        for (int it = 0; it < TOPK; it++)
            atomicOr(&g_adj[b * NN + sel[it]], 1ull << n);
    }
}

// ---------------- GAT ----------------
__global__ void gat_sd(const float* __restrict__ asrc, const float* __restrict__ adst) {
    int row = blockIdx.x;
    __shared__ float r1[HH], r2[HH];
    int t = threadIdx.x;
    float v = g_hw[(size_t)row * HH + t];
    r1[t] = v * asrc[t];
    r2[t] = v * adst[t];
    __syncthreads();
    for (int st = 128; st > 0; st >>= 1) {
        if (t < st) { r1[t] += r1[t + st]; r2[t] += r2[t + st]; }
        __syncthreads();
    }
    if (t == 0) { g_s[row] = r1[0]; g_d[row] = r2[0]; }
}

__global__ void gat_attn() {
    int b = blockIdx.x / NN, n = blockIdx.x % NN;
    __shared__ float attn[NN];
    __shared__ float inv_s;
    int t = threadIdx.x;
    unsigned long long mask = g_adj[b * NN + n];
    if (t < NN) {
        float e;
        if ((mask >> t) & 1ull) {
            float z = g_s[b * NN + n] + g_d[b * NN + t];
            e = z >= 0.f ? z : 0.2f * z;
        } else {
            e = -1e9f;
        }
        attn[t] = e;
    }
    __syncthreads();
    if (t == 0) {
        float mx = -INFINITY;
        for (int j = 0; j < NN; j++) mx = fmaxf(mx, attn[j]);
        float sum = 0.f;
        for (int j = 0; j < NN; j++) { float ex = expf(attn[j] - mx); attn[j] = ex; sum += ex; }
        inv_s = 1.f / sum;
    }
    __syncthreads();
    float inv = inv_s;
    float acc = 0.f;
    for (int m = 0; m < NN; m++)
        acc = fmaf(attn[m] * inv, g_hw[((size_t)b * NN + m) * HH + t], acc);
    float o = acc > 0.f ? acc : expm1f(acc);
    size_t oo = ((size_t)b * NN + n) * HH + t;
    float nh = g_hn[oo] + o;
    g_hn[oo] = nh;
    bf16 h, l;
    split_bf16(nh, h, l);
    g_hnh[oo] = h; g_hnl[oo] = l;
}

// ---------------- layernorm ----------------
__global__ void layernorm_k(const float* __restrict__ g, const float* __restrict__ bt) {
    int row = blockIdx.x;
    __shared__ float red[HH];
    __shared__ float mu_s, is_s;
    int t = threadIdx.x;
    float v = g_hn[(size_t)row * HH + t];
    red[t] = v;
    __syncthreads();
    for (int st = 128; st > 0; st >>= 1) { if (t < st) red[t] += red[t + st]; __syncthreads(); }
    if (t == 0) mu_s = red[0] * (1.f / HH);
    __syncthreads();
    float mu = mu_s;
    float dv = v - mu;
    red[t] = dv * dv;
    __syncthreads();
    for (int st = 128; st > 0; st >>= 1) { if (t < st) red[t] += red[t + st]; __syncthreads(); }
    if (t == 0) is_s = rsqrtf(red[0] * (1.f / HH) + 1e-5f);
    __syncthreads();
    g_ln[(size_t)row * HH + t] = dv * is_s * g[t] + bt[t];
}

// ---------------- pooling + classifier ----------------
__global__ void pool_emb(float* __restrict__ out) {
    int idx = blockIdx.x * blockDim.x + threadIdx.x;
    if (idx >= BB * HH) return;
    int b = idx / HH, c = idx % HH;
    float sm = 0.f, mx = -INFINITY;
    for (int n = 0; n < NN; n++) {
        float v = g_ln[((size_t)b * NN + n) * HH + c];
        sm += v;
        mx = fmaxf(mx, v);
    }
    out[BB * NCLS + (size_t)b * (2 * HH) + c] = sm * (1.f / NN);
    out[BB * NCLS + (size_t)b * (2 * HH) + HH + c] = mx;
}

__global__ void cls_kan(const float* __restrict__ cbw, const float* __restrict__ csw,
                        const float* __restrict__ csc, float* __restrict__ out) {
    int b = blockIdx.x;
    int t = threadIdx.x;
    __shared__ float r0[256], r1[256];
    float a0 = 0.f, a1 = 0.f;
    const float* emb = out + BB * NCLS + (size_t)b * (2 * HH);
    for (int i = t; i < 2 * HH; i += 256) {
        float x = emb[i];
        float sil = silu_f(x);
        float bs[8];
        bsplines8(x, bs);
        float p0 = sil * cbw[i];
        float p1 = sil * cbw[2 * HH + i];
        float s0 = csc[i], s1 = csc[2 * HH + i];
#pragma unroll
        for (int c = 0; c < 8; c++) {
            p0 = fmaf(bs[c] * csw[(size_t)i * 8 + c], s0, p0);
            p1 = fmaf(bs[c] * csw[(size_t)(2 * HH + i) * 8 + c], s1, p1);
        }
        a0 += p0;
        a1 += p1;
    }
    r0[t] = a0; r1[t] = a1;
    __syncthreads();
    for (int st = 128; st > 0; st >>= 1) {
        if (t < st) { r0[t] += r0[t + st]; r1[t] += r1[t + st]; }
        __syncthreads();
    }
    if (t == 0) { out[b * NCLS + 0] = r0[0]; out[b * NCLS + 1] = r1[0]; }
}

// ---------------- host launch ----------------
extern "C" void kernel_launch(void* const* d_in, const int* in_sizes, int n_in,
                              void* d_out, int out_size) {
    const float* x    = (const float*)d_in[0];
    const float* bbw  = (const float*)d_in[1];
    const float* bsw  = (const float*)d_in[2];
    const float* bsc  = (const float*)d_in[3];
    const float* c1w  = (const float*)d_in[4];
    const float* c1b  = (const float*)d_in[5];
    const float* c2w  = (const float*)d_in[6];
    const float* c2b  = (const float*)d_in[7];
    const float* pos  = (const float*)d_in[8];
    const float* gatW = (const float*)d_in[9];
    const float* asrc = (const float*)d_in[10];
    const float* adst = (const float*)d_in[11];
    const float* lng  = (const float*)d_in[12];
    const float* lnb  = (const float*)d_in[13];
    const float* cbw  = (const float*)d_in[14];
    const float* csw  = (const float*)d_in[15];
    const float* csc  = (const float*)d_in[16];
    float* out = (float*)d_out;

    bf16 *pwh, *pwl, *ph1h, *ph1l, *pwch, *pwcl, *py1h, *py1l, *phnh, *phnl, *pwth, *pwtl;
    float *py2, *phw;
    cudaGetSymbolAddress((void**)&pwh, g_wh);
    cudaGetSymbolAddress((void**)&pwl, g_wl);
    cudaGetSymbolAddress((void**)&ph1h, g_h1h);
    cudaGetSymbolAddress((void**)&ph1l, g_h1l);
    cudaGetSymbolAddress((void**)&pwch, g_wch);
    cudaGetSymbolAddress((void**)&pwcl, g_wcl);
    cudaGetSymbolAddress((void**)&py1h, g_y1h);
    cudaGetSymbolAddress((void**)&py1l, g_y1l);
    cudaGetSymbolAddress((void**)&phnh, g_hnh);
    cudaGetSymbolAddress((void**)&phnl, g_hnl);
    cudaGetSymbolAddress((void**)&pwth, g_wth);
    cudaGetSymbolAddress((void**)&pwtl, g_wtl);
    cudaGetSymbolAddress((void**)&py2, g_y2);
    cudaGetSymbolAddress((void**)&phw, g_hw);

    cudaFuncSetAttribute(bridge_gemm_fused, cudaFuncAttributeMaxDynamicSharedMemorySize, BR_SMEM);
    cudaFuncSetAttribute(gemm_mma<3, 1>, cudaFuncAttributeMaxDynamicSharedMemorySize, GEMM_SMEM);
    cudaFuncSetAttribute(gemm_mma<1, 1>, cudaFuncAttributeMaxDynamicSharedMemorySize, GEMM_SMEM);
    cudaFuncSetAttribute(gemm_mma<0, 0>, cudaFuncAttributeMaxDynamicSharedMemorySize, GEMM_SMEM);

    const int TPB = 256;

    // bridge: weights prep + fused feature-gen GEMM
    build_wcat_bf16<<<(HH * DIN + TPB - 1) / TPB, TPB>>>(bbw, bsw, bsc);
    bridge_gemm_fused<<<MROWS / 64, 256, BR_SMEM>>>(x, pwh, pwl, ph1h, ph1l);

    // conv1 (implicit im2col) + selu -> split bf16
    conv_w_bf16<<<(HH * HH + TPB - 1) / TPB, TPB>>>(c1w);
    gemm_mma<3, 1><<<MROWS / 64, 256, GEMM_SMEM>>>(ph1h, ph1l, pwch, pwcl,
                                                   nullptr, py1h, py1l, KCONV, c1b);

    // conv2 (implicit im2col) + selu -> fp32
    conv_w_bf16<<<(HH * HH + TPB - 1) / TPB, TPB>>>(c2w);
    gemm_mma<1, 1><<<MROWS / 64, 256, GEMM_SMEM>>>(py1h, py1l, pwch, pwcl,
                                                   py2, nullptr, nullptr, KCONV, c2b);

    // pool + pos (+ adj zero + split)
    pool_pos<<<(BB * NN * HH + TPB - 1) / TPB, TPB>>>(py2, pos);

    // adjacency
    adj_topk<<<BB * NN, NN>>>();

    // 2 residual GAT layers
    for (int L = 0; L < 2; L++) {
        gatwt_bf16<<<(HH * HH + TPB - 1) / TPB, TPB>>>(gatW + (size_t)L * HH * HH);
        gemm_mma<0, 0><<<NROWS / 64, 256, GEMM_SMEM>>>(phnh, phnl, pwth, pwtl,
                                                       phw, nullptr, nullptr, HH, nullptr);
        gat_sd<<<NROWS, HH>>>(asrc + L * HH, adst + L * HH);
        gat_attn<<<NROWS, HH>>>();
    }

    // layernorm + pooling + classifier
    layernorm_k<<<NROWS, HH>>>(lng, lnb);
    pool_emb<<<(BB * HH + TPB - 1) / TPB, TPB>>>(out);
    cls_kan<<<BB, 256>>>(cbw, csw, csc, out);
}

// round 6
// speedup vs baseline: 1.1113x; 1.1113x over previous
#include <cuda_runtime.h>
#include <cuda_bf16.h>
#include <math.h>
#include <stdint.h>

typedef __nv_bfloat16 bf16;

// ---------------- problem constants ----------------
#define BB 16
#define TT 512
#define DIN 1024
#define HH 256
#define NN 64
#define TOPK 8
#define NCLS 2
#define KBRIDGE (DIN * 9)      // 9216
#define KCONV (HH * 3)         // 768
#define MROWS (BB * TT)        // 8192
#define NROWS (BB * NN)        // 1024

// ---------------- PTX helpers ----------------
__device__ __forceinline__ uint32_t smem_u32(const void* p) {
    uint32_t a;
    asm("{ .reg .u64 t; cvta.to.shared.u64 t, %1; cvt.u32.u64 %0, t; }" : "=r"(a) : "l"(p));
    return a;
}
#define CP_ASYNC16(dst, src) \
    asm volatile("cp.async.cg.shared.global [%0], [%1], 16;" :: "r"(dst), "l"(src) : "memory")
#define CP_COMMIT() asm volatile("cp.async.commit_group;" ::: "memory")
#define CP_WAIT(N)  asm volatile("cp.async.wait_group %0;" :: "n"(N) : "memory")
#define LDSM_X4(r0, r1, r2, r3, a) \
    asm volatile("ldmatrix.sync.aligned.m8n8.x4.shared.b16 {%0,%1,%2,%3}, [%4];" \
        : "=r"(r0), "=r"(r1), "=r"(r2), "=r"(r3) : "r"(a))
#define MMA_BF16(c, a0, a1, a2, a3, b0, b1) \
    asm volatile("mma.sync.aligned.m16n8k16.row.col.f32.bf16.bf16.f32 " \
        "{%0,%1,%2,%3}, {%4,%5,%6,%7}, {%8,%9}, {%0,%1,%2,%3};" \
        : "+f"((c)[0]), "+f"((c)[1]), "+f"((c)[2]), "+f"((c)[3]) \
        : "r"(a0), "r"(a1), "r"(a2), "r"(a3), "r"(b0), "r"(b1))
#define STS128Z(addr) \
    asm volatile("st.shared.v4.b32 [%0], {%1,%1,%1,%1};" :: "r"(addr), "r"(0u) : "memory")

// ---------------- scratch ----------------
__device__ bf16 g_fh[(size_t)MROWS * KBRIDGE];   // feature matrix hi
__device__ bf16 g_fl[(size_t)MROWS * KBRIDGE];   // feature matrix lo
__device__ bf16 g_wh[HH * KBRIDGE];
__device__ bf16 g_wl[HH * KBRIDGE];
__device__ bf16 g_h1h[MROWS * HH];
__device__ bf16 g_h1l[MROWS * HH];
__device__ bf16 g_wch[HH * KCONV];
__device__ bf16 g_wcl[HH * KCONV];
__device__ bf16 g_y1h[MROWS * HH];
__device__ bf16 g_y1l[MROWS * HH];
__device__ float g_y2[MROWS * HH];
__device__ float g_hn[NROWS * HH];
__device__ bf16 g_hnh[NROWS * HH];
__device__ bf16 g_hnl[NROWS * HH];
__device__ bf16 g_wth[HH * HH];
__device__ bf16 g_wtl[HH * HH];
__device__ float g_hw[NROWS * HH];
__device__ float g_s[NROWS];
__device__ float g_d[NROWS];
__device__ unsigned long long g_adj[BB * NN];
__device__ float g_ln[NROWS * HH];

// ---------------- math helpers ----------------
__device__ __forceinline__ float silu_f(float x) { return x * (1.f / (1.f + expf(-x))); }
__device__ __forceinline__ float selu_f(float x) {
    const float a = 1.6732632423543772f, s = 1.0507009873554805f;
    return x > 0.f ? s * x : s * a * expm1f(x);
}
__device__ __forceinline__ void split_bf16(float v, bf16& h, bf16& l) {
    h = __float2bfloat16_rn(v);
    l = __float2bfloat16_rn(v - __bfloat162float(h));
}
union Pack2 { bf16 b[2]; uint32_t u; };
union Pack4 { bf16 b[4]; uint2 u; };
__device__ __forceinline__ uint32_t pack2(bf16 a, bf16 b) {
    Pack2 p; p.b[0] = a; p.b[1] = b; return p.u;
}
__device__ __forceinline__ void split_store4(const float* v, bf16* ph, bf16* pl) {
    Pack4 H, L;
#pragma unroll
    for (int j = 0; j < 4; j++) split_bf16(v[j], H.b[j], L.b[j]);
    *reinterpret_cast<uint2*>(ph) = H.u;
    *reinterpret_cast<uint2*>(pl) = L.u;
}
__device__ __forceinline__ void bsplines8(float x, float* out) {
    const float h = 0.4f;
    float b[11];
#pragma unroll
    for (int j = 0; j < 11; j++) {
        float gj = (float)(j - 3) * h - 1.0f;
        float gj1 = (float)(j - 2) * h - 1.0f;
        b[j] = (x >= gj && x < gj1) ? 1.f : 0.f;
    }
#pragma unroll
    for (int k = 1; k <= 3; k++) {
        float inv = 1.f / ((float)k * h);
#pragma unroll
        for (int j = 0; j < 11; j++) {
            if (j < 11 - k) {
                float gj = (float)(j - 3) * h - 1.0f;
                float gjk1 = (float)(j + k - 2) * h - 1.0f;
                b[j] = (x - gj) * inv * b[j] + (gjk1 - x) * inv * b[j + 1];
            }
        }
    }
#pragma unroll
    for (int j = 0; j < 8; j++) out[j] = b[j];
}

// ---------------- prep kernels ----------------
__global__ void bridge_features_bf16(const float* __restrict__ x) {
    int idx = blockIdx.x * blockDim.x + threadIdx.x;
    if (idx >= MROWS * (DIN / 4)) return;
    int r = idx >> 8, i4 = idx & 255;
    float4 xv = *reinterpret_cast<const float4*>(x + (size_t)r * DIN + i4 * 4);
    float vv[4] = {xv.x, xv.y, xv.z, xv.w};
    float f[9][4];
#pragma unroll
    for (int j = 0; j < 4; j++) {
        f[0][j] = silu_f(vv[j]);
        float bs[8];
        bsplines8(vv[j], bs);
#pragma unroll
        for (int c = 0; c < 8; c++) f[c + 1][j] = bs[c];
    }
    size_t base = (size_t)r * KBRIDGE + i4 * 4;
#pragma unroll
    for (int g = 0; g < 9; g++)
        split_store4(f[g], g_fh + base + (size_t)g * DIN, g_fl + base + (size_t)g * DIN);
}

__global__ void build_wcat_bf16(const float* __restrict__ bw, const float* __restrict__ sw,
                                const float* __restrict__ sc) {
    int idx = blockIdx.x * blockDim.x + threadIdx.x;
    if (idx >= HH * DIN) return;
    int i = idx % DIN, o = idx / DIN;
    size_t base = (size_t)o * KBRIDGE + i;
    bf16 h, l;
    split_bf16(bw[idx], h, l);
    g_wh[base] = h; g_wl[base] = l;
    float scale = sc[idx];
#pragma unroll
    for (int c = 0; c < 8; c++) {
        split_bf16(sw[(size_t)idx * 8 + c] * scale, h, l);
        size_t p = base + (size_t)(c + 1) * DIN;
        g_wh[p] = h; g_wl[p] = l;
    }
}

__global__ void conv_w_bf16(const float* __restrict__ w) {
    int idx = blockIdx.x * blockDim.x + threadIdx.x;
    if (idx >= HH * HH) return;
    int i = idx % HH, o = idx / HH;
#pragma unroll
    for (int j = 0; j < 3; j++) {
        bf16 h, l;
        split_bf16(w[((size_t)o * HH + i) * 3 + j], h, l);
        size_t p = (size_t)o * KCONV + j * HH + i;
        g_wch[p] = h; g_wcl[p] = l;
    }
}

__global__ void gatwt_bf16(const float* __restrict__ w) {
    int idx = blockIdx.x * blockDim.x + threadIdx.x;
    if (idx >= HH * HH) return;
    int k = idx % HH, n = idx / HH;
    bf16 h, l;
    split_bf16(w[(size_t)k * HH + n], h, l);
    g_wth[idx] = h; g_wtl[idx] = l;
}

// ================= split-bf16 GEMM, 512 threads (16 warps) =================
// C[m,n] = sum_k A[m,k]*B[n,k], hi/lo 3-product. Tile 64(M) x 256(N), BK=64.
// SHIFT=1: implicit im2col (A[row,k] = Y[row + k/256 - 1, k%256], zfill at edges).
// EPI: 0 raw fp32 | 1 selu+bias fp32 | 2 raw split bf16 | 3 selu+bias split bf16.
#define BK 64
#define SROW 144
#define A_STG (64 * SROW)        // 9216
#define B_STG (256 * SROW)       // 36864
#define GEMM_SMEM (4 * A_STG + 4 * B_STG)   // 184320

template <int EPI, int SHIFT>
__global__ __launch_bounds__(512, 1) void gemm_mma(
    const bf16* __restrict__ Ah, const bf16* __restrict__ Al,
    const bf16* __restrict__ Bh, const bf16* __restrict__ Bl,
    float* __restrict__ Cf, bf16* __restrict__ Ch, bf16* __restrict__ Cl,
    int K, const float* __restrict__ bias) {
    extern __shared__ char smem[];
    uint32_t s0 = smem_u32(smem);
    uint32_t sAh = s0, sAl = s0 + 2 * A_STG;
    uint32_t sBh = s0 + 4 * A_STG, sBl = sBh + 2 * B_STG;

    int tid = threadIdx.x, lane = tid & 31, wid = tid >> 5;
    int wm = wid & 1, wn = wid >> 1;       // 2 x 8 warp grid (32 rows x 32 cols each)
    int bm = blockIdx.x * 64;
    const int nc = K / BK;

    int aRow = wm * 32 + (lane & 15);
    int aCol = (lane >> 4) * 8;
    int bRow = wn * 32 + (lane & 7) + ((lane >> 4) << 3);
    int bCol = ((lane >> 3) & 1) * 8;

    float acc[2][4][4];
#pragma unroll
    for (int i = 0; i < 2; i++)
#pragma unroll
        for (int j = 0; j < 4; j++)
#pragma unroll
            for (int q = 0; q < 4; q++) acc[i][j][q] = 0.f;

    auto issue = [&](int stage, int k0) {
        {   // A: 64 rows x 8 chunks = 512 = one per thread per array
            int r = tid >> 3, c = tid & 7;
            uint32_t dh = sAh + (uint32_t)(stage * A_STG + r * SROW + c * 16);
            uint32_t dl = sAl + (uint32_t)(stage * A_STG + r * SROW + c * 16);
            if (SHIFT) {
                int k = k0 + c * 8;
                int j = k >> 8, cc = k & 255;
                int grow = bm + r;
                int tj = (grow & 511) + j - 1;
                if (tj >= 0 && tj < 512) {
                    size_t go = (size_t)(grow + j - 1) * 256 + cc;
                    CP_ASYNC16(dh, Ah + go);
                    CP_ASYNC16(dl, Al + go);
                } else {
                    STS128Z(dh);
                    STS128Z(dl);
                }
            } else {
                size_t go = (size_t)(bm + r) * K + k0 + c * 8;
                CP_ASYNC16(dh, Ah + go);
                CP_ASYNC16(dl, Al + go);
            }
        }
#pragma unroll
        for (int i = 0; i < 4; i++) {   // B: 256 rows x 8 chunks = 2048 per array
            int q = i * 512 + tid;
            int r = q >> 3, c = q & 7;
            uint32_t d = (uint32_t)(stage * B_STG + r * SROW + c * 16);
            size_t go = (size_t)r * K + k0 + c * 8;
            CP_ASYNC16(sBh + d, Bh + go);
            CP_ASYNC16(sBl + d, Bl + go);
        }
    };

    issue(0, 0);
    CP_COMMIT();

    for (int kc = 0; kc < nc; kc++) {
        if (kc + 1 < nc) {
            issue((kc + 1) & 1, (kc + 1) * BK);
            CP_COMMIT();
            CP_WAIT(1);
        } else {
            CP_WAIT(0);
        }
        __syncthreads();
        uint32_t stA = (uint32_t)((kc & 1) * A_STG);
        uint32_t stB = (uint32_t)((kc & 1) * B_STG);
#pragma unroll
        for (int kk = 0; kk < 4; kk++) {
            uint32_t ah[2][4], al[2][4];
#pragma unroll
            for (int mt = 0; mt < 2; mt++) {
                uint32_t ao = stA + (uint32_t)((aRow + mt * 16) * SROW + (aCol + kk * 16) * 2);
                LDSM_X4(ah[mt][0], ah[mt][1], ah[mt][2], ah[mt][3], sAh + ao);
                LDSM_X4(al[mt][0], al[mt][1], al[mt][2], al[mt][3], sAl + ao);
            }
#pragma unroll
            for (int nt2 = 0; nt2 < 2; nt2++) {
                uint32_t bo = stB + (uint32_t)((bRow + nt2 * 16) * SROW + (bCol + kk * 16) * 2);
                uint32_t bh[4], bl[4];
                LDSM_X4(bh[0], bh[1], bh[2], bh[3], sBh + bo);
                LDSM_X4(bl[0], bl[1], bl[2], bl[3], sBl + bo);
#pragma unroll
                for (int mt = 0; mt < 2; mt++) {
                    int n0 = nt2 * 2, n1 = n0 + 1;
                    MMA_BF16(acc[mt][n0], ah[mt][0], ah[mt][1], ah[mt][2], ah[mt][3], bh[0], bh[1]);
                    MMA_BF16(acc[mt][n0], ah[mt][0], ah[mt][1], ah[mt][2], ah[mt][3], bl[0], bl[1]);
                    MMA_BF16(acc[mt][n0], al[mt][0], al[mt][1], al[mt][2], al[mt][3], bh[0], bh[1]);
                    MMA_BF16(acc[mt][n1], ah[mt][0], ah[mt][1], ah[mt][2], ah[mt][3], bh[2], bh[3]);
                    MMA_BF16(acc[mt][n1], ah[mt][0], ah[mt][1], ah[mt][2], ah[mt][3], bl[2], bl[3]);
                    MMA_BF16(acc[mt][n1], al[mt][0], al[mt][1], al[mt][2], al[mt][3], bh[2], bh[3]);
                }
            }
        }
        __syncthreads();
    }

    // epilogue: warp covers rows [bm+wm*32, +32), cols [wn*32, +32)
    int rbase = bm + wm * 32 + (lane >> 2);
    int cbase = wn * 32 + (lane & 3) * 2;
#pragma unroll
    for (int mt = 0; mt < 2; mt++) {
#pragma unroll
        for (int nt = 0; nt < 4; nt++) {
            int r = rbase + mt * 16;
            int c = cbase + nt * 8;
            float v0 = acc[mt][nt][0], v1 = acc[mt][nt][1];
            float w0 = acc[mt][nt][2], w1 = acc[mt][nt][3];
            if (EPI == 1 || EPI == 3) {
                float b0 = bias[c], b1 = bias[c + 1];
                v0 = selu_f(v0 + b0); v1 = selu_f(v1 + b1);
                w0 = selu_f(w0 + b0); w1 = selu_f(w1 + b1);
            }
            if (EPI >= 2) {
                bf16 h0, l0, h1, l1;
                split_bf16(v0, h0, l0); split_bf16(v1, h1, l1);
                *reinterpret_cast<uint32_t*>(Ch + (size_t)r * 256 + c) = pack2(h0, h1);
                *reinterpret_cast<uint32_t*>(Cl + (size_t)r * 256 + c) = pack2(l0, l1);
                split_bf16(w0, h0, l0); split_bf16(w1, h1, l1);
                *reinterpret_cast<uint32_t*>(Ch + (size_t)(r + 8) * 256 + c) = pack2(h0, h1);
                *reinterpret_cast<uint32_t*>(Cl + (size_t)(r + 8) * 256 + c) = pack2(l0, l1);
            } else {
                *reinterpret_cast<float2*>(Cf + (size_t)r * 256 + c) = make_float2(v0, v1);
                *reinterpret_cast<float2*>(Cf + (size_t)(r + 8) * 256 + c) = make_float2(w0, w1);
            }
        }
    }
}

// ---------------- pool + pos (+ adj zero, + split) ----------------
__global__ void pool_pos(const float* __restrict__ y2, const float* __restrict__ pos) {
    int idx = blockIdx.x * blockDim.x + threadIdx.x;
    if (idx < BB * NN) g_adj[idx] = 0ull;
    if (idx >= BB * NN * HH) return;
    int c = idx % HH;
    int n = (idx / HH) % NN;
    int b = idx / (HH * NN);
    float s = 0.f;
#pragma unroll
    for (int t = 0; t < 8; t++) s += y2[((size_t)b * TT + n * 8 + t) * HH + c];
    float v = s * 0.125f + pos[(size_t)n * HH + c];
    size_t o = ((size_t)b * NN + n) * HH + c;
    g_hn[o] = v;
    bf16 h, l;
    split_bf16(v, h, l);
    g_hnh[o] = h; g_hnl[o] = l;
}

// ---------------- adjacency ----------------
__global__ void adj_topk() {
    int b = blockIdx.x / NN, n = blockIdx.x % NN;
    __shared__ float sc[NN];
    int m = threadIdx.x;
    const float* hb = g_hn + (size_t)b * NN * HH;
    float s = 0.f;
    for (int k = 0; k < HH; k++) s = fmaf(hb[(size_t)n * HH + k], hb[(size_t)m * HH + k], s);
    sc[m] = s;
    __syncthreads();
    if (m == 0) {
        unsigned long long mask = 1ull << n;
        int sel[TOPK];
#pragma unroll 1
        for (int it = 0; it < TOPK; it++) {
            float best = -INFINITY; int bi = 0;
            for (int j = 0; j < NN; j++)
                if (sc[j] > best) { best = sc[j]; bi = j; }
            sel[it] = bi;
            sc[bi] = -INFINITY;
            mask |= 1ull << bi;
        }
        atomicOr(&g_adj[b * NN + n], mask);
        for (int it = 0; it < TOPK; it++)
            atomicOr(&g_adj[b * NN + sel[it]], 1ull << n);
    }
}

// ---------------- GAT ----------------
__global__ void gat_sd(const float* __restrict__ asrc, const float* __restrict__ adst) {
    int row = blockIdx.x;
    __shared__ float r1[HH], r2[HH];
    int t = threadIdx.x;
    float v = g_hw[(size_t)row * HH + t];
    r1[t] = v * asrc[t];
    r2[t] = v * adst[t];
    __syncthreads();
    for (int st = 128; st > 0; st >>= 1) {
        if (t < st) { r1[t] += r1[t + st]; r2[t] += r2[t + st]; }
        __syncthreads();
    }
    if (t == 0) { g_s[row] = r1[0]; g_d[row] = r2[0]; }
}

__global__ void gat_attn() {
    int b = blockIdx.x / NN, n = blockIdx.x % NN;
    __shared__ float attn[NN];
    __shared__ float inv_s;
    int t = threadIdx.x;
    unsigned long long mask = g_adj[b * NN + n];
    if (t < NN) {
        float e;
        if ((mask >> t) & 1ull) {
            float z = g_s[b * NN + n] + g_d[b * NN + t];
            e = z >= 0.f ? z : 0.2f * z;
        } else {
            e = -1e9f;
        }
        attn[t] = e;
    }
    __syncthreads();
    if (t == 0) {
        float mx = -INFINITY;
        for (int j = 0; j < NN; j++) mx = fmaxf(mx, attn[j]);
        float sum = 0.f;
        for (int j = 0; j < NN; j++) { float ex = expf(attn[j] - mx); attn[j] = ex; sum += ex; }
        inv_s = 1.f / sum;
    }
    __syncthreads();
    float inv = inv_s;
    float acc = 0.f;
    for (int m = 0; m < NN; m++)
        acc = fmaf(attn[m] * inv, g_hw[((size_t)b * NN + m) * HH + t], acc);
    float o = acc > 0.f ? acc : expm1f(acc);
    size_t oo = ((size_t)b * NN + n) * HH + t;
    float nh = g_hn[oo] + o;
    g_hn[oo] = nh;
    bf16 h, l;
    split_bf16(nh, h, l);
    g_hnh[oo] = h; g_hnl[oo] = l;
}

// ---------------- layernorm ----------------
__global__ void layernorm_k(const float* __restrict__ g, const float* __restrict__ bt) {
    int row = blockIdx.x;
    __shared__ float red[HH];
    __shared__ float mu_s, is_s;
    int t = threadIdx.x;
    float v = g_hn[(size_t)row * HH + t];
    red[t] = v;
    __syncthreads();
    for (int st = 128; st > 0; st >>= 1) { if (t < st) red[t] += red[t + st]; __syncthreads(); }
    if (t == 0) mu_s = red[0] * (1.f / HH);
    __syncthreads();
    float mu = mu_s;
    float dv = v - mu;
    red[t] = dv * dv;
    __syncthreads();
    for (int st = 128; st > 0; st >>= 1) { if (t < st) red[t] += red[t + st]; __syncthreads(); }
    if (t == 0) is_s = rsqrtf(red[0] * (1.f / HH) + 1e-5f);
    __syncthreads();
    g_ln[(size_t)row * HH + t] = dv * is_s * g[t] + bt[t];
}

// ---------------- pooling + classifier ----------------
__global__ void pool_emb(float* __restrict__ out) {
    int idx = blockIdx.x * blockDim.x + threadIdx.x;
    if (idx >= BB * HH) return;
    int b = idx / HH, c = idx % HH;
    float sm = 0.f, mx = -INFINITY;
    for (int n = 0; n < NN; n++) {
        float v = g_ln[((size_t)b * NN + n) * HH + c];
        sm += v;
        mx = fmaxf(mx, v);
    }
    out[BB * NCLS + (size_t)b * (2 * HH) + c] = sm * (1.f / NN);
    out[BB * NCLS + (size_t)b * (2 * HH) + HH + c] = mx;
}

__global__ void cls_kan(const float* __restrict__ cbw, const float* __restrict__ csw,
                        const float* __restrict__ csc, float* __restrict__ out) {
    int b = blockIdx.x;
    int t = threadIdx.x;
    __shared__ float r0[256], r1[256];
    float a0 = 0.f, a1 = 0.f;
    const float* emb = out + BB * NCLS + (size_t)b * (2 * HH);
    for (int i = t; i < 2 * HH; i += 256) {
        float x = emb[i];
        float sil = silu_f(x);
        float bs[8];
        bsplines8(x, bs);
        float p0 = sil * cbw[i];
        float p1 = sil * cbw[2 * HH + i];
        float s0 = csc[i], s1 = csc[2 * HH + i];
#pragma unroll
        for (int c = 0; c < 8; c++) {
            p0 = fmaf(bs[c] * csw[(size_t)i * 8 + c], s0, p0);
            p1 = fmaf(bs[c] * csw[(size_t)(2 * HH + i) * 8 + c], s1, p1);
        }
        a0 += p0;
        a1 += p1;
    }
    r0[t] = a0; r1[t] = a1;
    __syncthreads();
    for (int st = 128; st > 0; st >>= 1) {
        if (t < st) { r0[t] += r0[t + st]; r1[t] += r1[t + st]; }
        __syncthreads();
    }
    if (t == 0) { out[b * NCLS + 0] = r0[0]; out[b * NCLS + 1] = r1[0]; }
}

// ---------------- host launch ----------------
extern "C" void kernel_launch(void* const* d_in, const int* in_sizes, int n_in,
                              void* d_out, int out_size) {
    const float* x    = (const float*)d_in[0];
    const float* bbw  = (const float*)d_in[1];
    const float* bsw  = (const float*)d_in[2];
    const float* bsc  = (const float*)d_in[3];
    const float* c1w  = (const float*)d_in[4];
    const float* c1b  = (const float*)d_in[5];
    const float* c2w  = (const float*)d_in[6];
    const float* c2b  = (const float*)d_in[7];
    const float* pos  = (const float*)d_in[8];
    const float* gatW = (const float*)d_in[9];
    const float* asrc = (const float*)d_in[10];
    const float* adst = (const float*)d_in[11];
    const float* lng  = (const float*)d_in[12];
    const float* lnb  = (const float*)d_in[13];
    const float* cbw  = (const float*)d_in[14];
    const float* csw  = (const float*)d_in[15];
    const float* csc  = (const float*)d_in[16];
    float* out = (float*)d_out;

    bf16 *pfh, *pfl, *pwh, *pwl, *ph1h, *ph1l, *pwch, *pwcl, *py1h, *py1l, *phnh, *phnl, *pwth, *pwtl;
    float *py2, *phw;
    cudaGetSymbolAddress((void**)&pfh, g_fh);
    cudaGetSymbolAddress((void**)&pfl, g_fl);
    cudaGetSymbolAddress((void**)&pwh, g_wh);
    cudaGetSymbolAddress((void**)&pwl, g_wl);
    cudaGetSymbolAddress((void**)&ph1h, g_h1h);
    cudaGetSymbolAddress((void**)&ph1l, g_h1l);
    cudaGetSymbolAddress((void**)&pwch, g_wch);
    cudaGetSymbolAddress((void**)&pwcl, g_wcl);
    cudaGetSymbolAddress((void**)&py1h, g_y1h);
    cudaGetSymbolAddress((void**)&py1l, g_y1l);
    cudaGetSymbolAddress((void**)&phnh, g_hnh);
    cudaGetSymbolAddress((void**)&phnl, g_hnl);
    cudaGetSymbolAddress((void**)&pwth, g_wth);
    cudaGetSymbolAddress((void**)&pwtl, g_wtl);
    cudaGetSymbolAddress((void**)&py2, g_y2);
    cudaGetSymbolAddress((void**)&phw, g_hw);

    cudaFuncSetAttribute(gemm_mma<2, 0>, cudaFuncAttributeMaxDynamicSharedMemorySize, GEMM_SMEM);
    cudaFuncSetAttribute(gemm_mma<3, 1>, cudaFuncAttributeMaxDynamicSharedMemorySize, GEMM_SMEM);
    cudaFuncSetAttribute(gemm_mma<1, 1>, cudaFuncAttributeMaxDynamicSharedMemorySize, GEMM_SMEM);
    cudaFuncSetAttribute(gemm_mma<0, 0>, cudaFuncAttributeMaxDynamicSharedMemorySize, GEMM_SMEM);

    const int TPB = 256;

    // bridge: features + weights prep + GEMM (raw -> split bf16)
    bridge_features_bf16<<<MROWS * (DIN / 4) / TPB, TPB>>>(x);
    build_wcat_bf16<<<(HH * DIN + TPB - 1) / TPB, TPB>>>(bbw, bsw, bsc);
    gemm_mma<2, 0><<<MROWS / 64, 512, GEMM_SMEM>>>(pfh, pfl, pwh, pwl,
                                                   nullptr, ph1h, ph1l, KBRIDGE, nullptr);

    // conv1 (implicit im2col) + selu -> split bf16
    conv_w_bf16<<<(HH * HH + TPB - 1) / TPB, TPB>>>(c1w);
    gemm_mma<3, 1><<<MROWS / 64, 512, GEMM_SMEM>>>(ph1h, ph1l, pwch, pwcl,
                                                   nullptr, py1h, py1l, KCONV, c1b);

    // conv2 (implicit im2col) + selu -> fp32
    conv_w_bf16<<<(HH * HH + TPB - 1) / TPB, TPB>>>(c2w);
    gemm_mma<1, 1><<<MROWS / 64, 512, GEMM_SMEM>>>(py1h, py1l, pwch, pwcl,
                                                   py2, nullptr, nullptr, KCONV, c2b);

    // pool + pos (+ adj zero + split)
    pool_pos<<<(BB * NN * HH + TPB - 1) / TPB, TPB>>>(py2, pos);

    // adjacency
    adj_topk<<<BB * NN, NN>>>();

    // 2 residual GAT layers
    for (int L = 0; L < 2; L++) {
        gatwt_bf16<<<(HH * HH + TPB - 1) / TPB, TPB>>>(gatW + (size_t)L * HH * HH);
        gemm_mma<0, 0><<<NROWS / 64, 512, GEMM_SMEM>>>(phnh, phnl, pwth, pwtl,
                                                       phw, nullptr, nullptr, HH, nullptr);
        gat_sd<<<NROWS, HH>>>(asrc + L * HH, adst + L * HH);
        gat_attn<<<NROWS, HH>>>();
    }

    // layernorm + pooling + classifier
    layernorm_k<<<NROWS, HH>>>(lng, lnb);
    pool_emb<<<(BB * HH + TPB - 1) / TPB, TPB>>>(out);
    cls_kan<<<BB, 256>>>(cbw, csw, csc, out);
}